// round 12
// baseline (speedup 1.0000x reference)
#include <cuda_runtime.h>
#include <cuda_bf16.h>

#define NN   50000
#define EE   800000
#define NEG  0.2f

// ---------------- scratch (static device arrays; no allocation allowed) ----
__device__ float g_xl1 [NN*128];
__device__ float g_xr1 [NN*128];
__device__ float g_h1  [NN*128];
__device__ float g_xl2 [NN*128];
__device__ float g_xr2 [NN*128];
__device__ float g_xres[NN*16];
__device__ int   g_deg [NN];
__device__ int   g_rowptr[NN+1];
__device__ int   g_cursor[NN];
__device__ int   g_csr [EE];

// ---------------- CSR build ------------------------------------------------
__global__ void k_zero_deg() {
    int i = blockIdx.x*256 + threadIdx.x;
    if (i < NN) g_deg[i] = 0;
}

// edge_index is int32 (JAX x64 disabled): row 0 = src [0..E), row 1 = dst [E..2E)
__global__ void k_count(const int* __restrict__ ei) {
    int e = blockIdx.x*256 + threadIdx.x;
    if (e < EE) {
        unsigned dst = (unsigned)ei[EE + e];
        if (dst < NN) atomicAdd(&g_deg[dst], 1);
    }
}

__global__ void __launch_bounds__(1024) k_scan() {
    __shared__ int s[1024];
    const int tid = threadIdx.x;
    const int per = (NN + 1023) / 1024;          // 49
    int start = tid * per;
    int stop  = min(start + per, NN);
    int sum = 0;
    for (int i = start; i < stop; i++) sum += g_deg[i];
    s[tid] = sum;
    __syncthreads();
    for (int off = 1; off < 1024; off <<= 1) {
        int v = (tid >= off) ? s[tid - off] : 0;
        __syncthreads();
        s[tid] += v;
        __syncthreads();
    }
    int run = s[tid] - sum;                      // exclusive offset for this chunk
    for (int i = start; i < stop; i++) {
        g_rowptr[i] = run;
        g_cursor[i] = run;
        run += g_deg[i];
    }
    // total kept edges = last thread's post-loop running value (inclusive total)
    if (tid == 1023) g_rowptr[NN] = run;
}

__global__ void k_scatter(const int* __restrict__ ei) {
    int e = blockIdx.x*256 + threadIdx.x;
    if (e < EE) {
        unsigned src = (unsigned)ei[e];
        unsigned dst = (unsigned)ei[EE + e];
        if (dst < NN && src < NN) {
            int pos = atomicAdd(&g_cursor[dst], 1);
            g_csr[pos] = (int)src;
        }
    }
}

// ---------------- SIMT GEMM: 128 nodes/block, in-kernel out-chunk loop ------
// Block loads its X tile ONCE, then iterates over out-chunks of 64, reloading
// only the W buffer each time. smem ~102KB -> 2 blocks/SM.
__device__ __forceinline__ void dot4(const float4 a, const float4 b, float& d) {
    d = fmaf(a.x, b.x, d);
    d = fmaf(a.y, b.y, d);
    d = fmaf(a.z, b.z, d);
    d = fmaf(a.w, b.w, d);
}

#define XSTR 132
#define WSTR 132

__global__ void __launch_bounds__(256) k_gemm(
    const float* __restrict__ A,
    const float* __restrict__ W0, const float* __restrict__ B0,
    const float* __restrict__ W1, const float* __restrict__ B1,
    const float* __restrict__ W2,
    float* __restrict__ O0, float* __restrict__ O1, float* __restrict__ O2,
    int nchunks)   // 5 (incl. 16-row skip chunk) or 4
{
    extern __shared__ float sm[];
    float* sW = sm;                    // 64*WSTR
    float* sX = sW + 64*WSTR;          // 128*XSTR
    float* sB = sX + 128*XSTR;         // 64

    const int tid = threadIdx.x;

    // X tile (128 nodes) -> smem, once
    const int n0 = blockIdx.x * 128;
    for (int i = tid; i < 4096; i += 256) {
        int r = i >> 5, q = i & 31;
        int n = n0 + r;
        float4 v = make_float4(0.f, 0.f, 0.f, 0.f);
        if (n < NN) v = ((const float4*)(A + (size_t)n * 128))[q];
        ((float4*)(sX + r*XSTR))[q] = v;
    }

    const int tx = tid & 15;          // node lane: nodes tx + 16*i, i=0..7
    const int ty = tid >> 4;          // out group: outs ty*4 .. ty*4+3

    for (int ch = 0; ch < nchunks; ch++) {
        const int ob   = ch * 64;
        const int rows = (ob >= 256) ? 16 : 64;

        const float* Wsrc; const float* Bsrc;
        if (ob < 128)      { Wsrc = W0 + ob*128;       Bsrc = B0 + ob; }
        else if (ob < 256) { Wsrc = W1 + (ob-128)*128; Bsrc = B1 + (ob-128); }
        else               { Wsrc = W2;                Bsrc = nullptr; }

        if (ch > 0) __syncthreads();   // all reads of previous sW done
        const float4* wg = (const float4*)Wsrc;
        for (int i = tid; i < rows*32; i += 256) {
            int r = i >> 5, q = i & 31;
            ((float4*)(sW + r*WSTR))[q] = wg[r*32 + q];
        }
        if (tid < 64) sB[tid] = (tid < rows && Bsrc) ? Bsrc[tid] : 0.f;
        __syncthreads();

        if (ty * 4 < rows) {
            float acc[8][4];
            #pragma unroll
            for (int i = 0; i < 8; i++)
                #pragma unroll
                for (int j = 0; j < 4; j++) acc[i][j] = 0.f;

            const float4* wp0 = (const float4*)(sW + (ty*4 + 0) * WSTR);
            const float4* wp1 = (const float4*)(sW + (ty*4 + 1) * WSTR);
            const float4* wp2 = (const float4*)(sW + (ty*4 + 2) * WSTR);
            const float4* wp3 = (const float4*)(sW + (ty*4 + 3) * WSTR);

            #pragma unroll 2
            for (int kq = 0; kq < 32; kq++) {
                float4 wv0 = wp0[kq], wv1 = wp1[kq], wv2 = wp2[kq], wv3 = wp3[kq];
                #pragma unroll
                for (int i = 0; i < 8; i++) {
                    float4 xv = ((const float4*)(sX + (tx + 16*i) * XSTR))[kq];
                    dot4(xv, wv0, acc[i][0]);
                    dot4(xv, wv1, acc[i][1]);
                    dot4(xv, wv2, acc[i][2]);
                    dot4(xv, wv3, acc[i][3]);
                }
            }

            #pragma unroll
            for (int j = 0; j < 4; j++) {
                int o = ob + ty*4 + j;
                float bv = sB[ty*4 + j];
                #pragma unroll
                for (int i = 0; i < 8; i++) {
                    int n = n0 + tx + 16*i;
                    if (n >= NN) continue;
                    float v = acc[i][j] + bv;
                    if (o < 128)      O0[(size_t)n * 128 + o]       = v;
                    else if (o < 256) O1[(size_t)n * 128 + (o-128)] = v;
                    else              O2[(size_t)n * 16  + (o-256)] = v;
                }
            }
        }
    }
}

// ---------------- per-node attention aggregation ----------------------------
// block = 128 threads, thread t = (head h = t>>4, channel c = t&15)
// Self-loop score as fixed softmax baseline -> edges independent.
// Edge indices read via uniform LDG (L1 broadcast) with 4-ahead prefetch;
// no smem staging, no barriers.
__device__ __forceinline__ float head_sum16(float p) {
    p += __shfl_xor_sync(0xffffffffu, p, 8);
    p += __shfl_xor_sync(0xffffffffu, p, 4);
    p += __shfl_xor_sync(0xffffffffu, p, 2);
    p += __shfl_xor_sync(0xffffffffu, p, 1);
    return p;
}

__device__ __forceinline__ void agg_body(
    const float* __restrict__ xlbuf, const int* __restrict__ csr,
    float xr, float attv, float xlv,
    int beg, int end, int t, float& den_out, float& acc_out)
{
    float e = xlv + xr; e = (e > 0.f) ? e : NEG * e;
    const float m0 = head_sum16(e * attv);    // self-loop score = baseline
    float den = 1.f;                           // exp(m0 - m0)
    float acc = xlv;

    int j = beg;
    int ia = 0, ib = 0, ic = 0, id = 0;
    if (j + 4 <= end) { ia = csr[j]; ib = csr[j+1]; ic = csr[j+2]; id = csr[j+3]; }
    while (j + 4 <= end) {
        int na = 0, nb = 0, nc2 = 0, nd = 0;
        const bool more = (j + 8 <= end);
        if (more) { na = csr[j+4]; nb = csr[j+5]; nc2 = csr[j+6]; nd = csr[j+7]; }

        float xa = xlbuf[(size_t)ia * 128 + t];
        float xb = xlbuf[(size_t)ib * 128 + t];
        float xc = xlbuf[(size_t)ic * 128 + t];
        float xd = xlbuf[(size_t)id * 128 + t];
        float ea = xa + xr; ea = (ea > 0.f) ? ea : NEG * ea;
        float eb = xb + xr; eb = (eb > 0.f) ? eb : NEG * eb;
        float ec = xc + xr; ec = (ec > 0.f) ? ec : NEG * ec;
        float ed = xd + xr; ed = (ed > 0.f) ? ed : NEG * ed;
        float sa = head_sum16(ea * attv);
        float sb = head_sum16(eb * attv);
        float sc = head_sum16(ec * attv);
        float sd = head_sum16(ed * attv);
        float wa = __expf(sa - m0);
        float wb = __expf(sb - m0);
        float wc = __expf(sc - m0);
        float wd = __expf(sd - m0);
        den += (wa + wb) + (wc + wd);
        acc = fmaf(wa, xa, fmaf(wb, xb, fmaf(wc, xc, fmaf(wd, xd, acc))));

        j += 4;
        ia = na; ib = nb; ic = nc2; id = nd;
    }
    for (; j < end; j++) {
        int i0 = csr[j];
        float xa = xlbuf[(size_t)i0 * 128 + t];
        float ea = xa + xr; ea = (ea > 0.f) ? ea : NEG * ea;
        float sa = head_sum16(ea * attv);
        float wa = __expf(sa - m0);
        den += wa;
        acc = fmaf(wa, xa, acc);
    }
    den_out = den; acc_out = acc;
}

__global__ void __launch_bounds__(128) k_agg1(
    const float* __restrict__ att,  const float* __restrict__ bias,
    const float* __restrict__ bnw,  const float* __restrict__ bnb,
    const float* __restrict__ bnrm, const float* __restrict__ bnrv)
{
    const int d = blockIdx.x;
    const int t = threadIdx.x;

    const float xr   = g_xr1[(size_t)d * 128 + t];
    const float attv = att[t];
    const float xlv  = g_xl1[(size_t)d * 128 + t];

    float den, acc;
    agg_body(g_xl1, g_csr, xr, attv, xlv, g_rowptr[d], g_rowptr[d + 1], t, den, acc);

    float val = acc / den + bias[t];
    val = (val - bnrm[t]) * rsqrtf(bnrv[t] + 1e-5f) * bnw[t] + bnb[t];   // BN eval
    val = (val > 0.f) ? val : (__expf(val) - 1.f);                       // ELU
    g_h1[(size_t)d * 128 + t] = val;
}

__global__ void __launch_bounds__(128) k_agg2(
    const float* __restrict__ att, const float* __restrict__ bias2,
    const float* __restrict__ lnw, const float* __restrict__ lnb,
    float* __restrict__ out)
{
    __shared__ float s_acc[128];
    const int d = blockIdx.x;
    const int t = threadIdx.x;

    const float xr   = g_xr2[(size_t)d * 128 + t];
    const float attv = att[t];
    const float xlv  = g_xl2[(size_t)d * 128 + t];

    float den, acc;
    agg_body(g_xl2, g_csr, xr, attv, xlv, g_rowptr[d], g_rowptr[d + 1], t, den, acc);

    s_acc[t] = acc / den;
    __syncthreads();
    if (t < 16) {
        float v = 0.f;
        #pragma unroll
        for (int h = 0; h < 8; h++) v += s_acc[h * 16 + t];
        v = v * 0.125f + bias2[t] + g_xres[(size_t)d * 16 + t];   // mean heads + bias + skip
        // LayerNorm over 16 channels (lanes 0..15 of warp 0)
        float mu = v;
        mu += __shfl_xor_sync(0xffffu, mu, 8);
        mu += __shfl_xor_sync(0xffffu, mu, 4);
        mu += __shfl_xor_sync(0xffffu, mu, 2);
        mu += __shfl_xor_sync(0xffffu, mu, 1);
        mu *= (1.f / 16.f);
        float dlt = v - mu;
        float var = dlt * dlt;
        var += __shfl_xor_sync(0xffffu, var, 8);
        var += __shfl_xor_sync(0xffffu, var, 4);
        var += __shfl_xor_sync(0xffffu, var, 2);
        var += __shfl_xor_sync(0xffffu, var, 1);
        var *= (1.f / 16.f);
        out[(size_t)d * 16 + t] = dlt * rsqrtf(var + 1e-5f) * lnw[t] + lnb[t];
    }
}

// ---------------- host ------------------------------------------------------
extern "C" void kernel_launch(void* const* d_in, const int* in_sizes, int n_in,
                              void* d_out, int out_size)
{
    const float* x     = (const float*)d_in[0];
    const int*   ei    = (const int*)d_in[1];      // int32: JAX x64 disabled
    const float* Wl1   = (const float*)d_in[2];
    const float* bl1   = (const float*)d_in[3];
    const float* Wr1   = (const float*)d_in[4];
    const float* br1   = (const float*)d_in[5];
    const float* att1  = (const float*)d_in[6];
    const float* bias1 = (const float*)d_in[7];
    const float* bnw   = (const float*)d_in[8];
    const float* bnb   = (const float*)d_in[9];
    const float* bnrm  = (const float*)d_in[10];
    const float* bnrv  = (const float*)d_in[11];
    const float* Wl2   = (const float*)d_in[12];
    const float* bl2   = (const float*)d_in[13];
    const float* Wr2   = (const float*)d_in[14];
    const float* br2   = (const float*)d_in[15];
    const float* att2  = (const float*)d_in[16];
    const float* bias2 = (const float*)d_in[17];
    const float* Wskip = (const float*)d_in[18];
    const float* lnw   = (const float*)d_in[19];
    const float* lnb   = (const float*)d_in[20];
    float*       out   = (float*)d_out;

    float *xl1, *xr1, *h1, *xl2, *xr2, *xres;
    cudaGetSymbolAddress((void**)&xl1,  g_xl1);
    cudaGetSymbolAddress((void**)&xr1,  g_xr1);
    cudaGetSymbolAddress((void**)&h1,   g_h1);
    cudaGetSymbolAddress((void**)&xl2,  g_xl2);
    cudaGetSymbolAddress((void**)&xr2,  g_xr2);
    cudaGetSymbolAddress((void**)&xres, g_xres);

    const int smem = (64*WSTR + 128*XSTR + 64) * 4;   // ~101.6 KB
    cudaFuncSetAttribute(k_gemm, cudaFuncAttributeMaxDynamicSharedMemorySize, smem);

    // CSR build (recomputed each call; deterministic)
    k_zero_deg<<<(NN + 255) / 256, 256>>>();
    k_count<<<(EE + 255) / 256, 256>>>(ei);
    k_scan<<<1, 1024>>>();
    k_scatter<<<(EE + 255) / 256, 256>>>(ei);

    const int NTILES = (NN + 127) / 128;   // 391

    // conv1 transforms + skip projection (272 outs -> 5 chunks, in-kernel loop)
    k_gemm<<<NTILES, 256, smem>>>(x, Wl1, bl1, Wr1, br1, Wskip,
                                  xl1, xr1, xres, 5);
    // conv1 aggregation + BN + ELU
    k_agg1<<<NN, 128>>>(att1, bias1, bnw, bnb, bnrm, bnrv);

    // conv2 transforms (256 outs -> 4 chunks)
    k_gemm<<<NTILES, 256, smem>>>(h1, Wl2, bl2, Wr2, br2, nullptr,
                                  xl2, xr2, nullptr, 4);
    // conv2 aggregation + head-mean + skip + LayerNorm
    k_agg2<<<NN, 128>>>(att2, bias2, lnw, lnb, out);
}

// round 15
// speedup vs baseline: 1.3621x; 1.3621x over previous
#include <cuda_runtime.h>
#include <cuda_bf16.h>

#define NN   50000
#define EE   800000
#define NEG  0.2f

// ---------------- scratch (static device arrays; no allocation allowed) ----
__device__ float g_xl1 [NN*128];
__device__ float g_xr1 [NN*128];
__device__ float g_h1  [NN*128];
__device__ float g_xl2 [NN*128];
__device__ float g_xr2 [NN*128];
__device__ float g_xres[NN*16];
__device__ int   g_deg [NN];
__device__ int   g_rowptr[NN+1];
__device__ int   g_cursor[NN];
__device__ int   g_csr [EE];

// ---------------- CSR build ------------------------------------------------
__global__ void k_zero_deg() {
    int i = blockIdx.x*256 + threadIdx.x;
    if (i < NN) g_deg[i] = 0;
}

// edge_index is int32 (JAX x64 disabled): row 0 = src [0..E), row 1 = dst [E..2E)
__global__ void k_count(const int* __restrict__ ei) {
    int e = blockIdx.x*256 + threadIdx.x;
    if (e < EE) {
        unsigned dst = (unsigned)ei[EE + e];
        if (dst < NN) atomicAdd(&g_deg[dst], 1);
    }
}

__global__ void __launch_bounds__(1024) k_scan() {
    __shared__ int s[1024];
    const int tid = threadIdx.x;
    const int per = (NN + 1023) / 1024;          // 49
    int start = tid * per;
    int stop  = min(start + per, NN);
    int sum = 0;
    for (int i = start; i < stop; i++) sum += g_deg[i];
    s[tid] = sum;
    __syncthreads();
    for (int off = 1; off < 1024; off <<= 1) {
        int v = (tid >= off) ? s[tid - off] : 0;
        __syncthreads();
        s[tid] += v;
        __syncthreads();
    }
    int run = s[tid] - sum;                      // exclusive offset for this chunk
    for (int i = start; i < stop; i++) {
        g_rowptr[i] = run;
        g_cursor[i] = run;
        run += g_deg[i];
    }
    // total kept edges = last thread's post-loop running value (inclusive total)
    if (tid == 1023) g_rowptr[NN] = run;
}

__global__ void k_scatter(const int* __restrict__ ei) {
    int e = blockIdx.x*256 + threadIdx.x;
    if (e < EE) {
        unsigned src = (unsigned)ei[e];
        unsigned dst = (unsigned)ei[EE + e];
        if (dst < NN && src < NN) {
            int pos = atomicAdd(&g_cursor[dst], 1);
            g_csr[pos] = (int)src;
        }
    }
}

// ---------------- SIMT GEMM: 128 nodes x 64 outs per block (R11 form) -------
// gridDim.x = node tiles, gridDim.y = out chunks of 64 over concat [W0;W1;W2].
__device__ __forceinline__ void dot4(const float4 a, const float4 b, float& d) {
    d = fmaf(a.x, b.x, d);
    d = fmaf(a.y, b.y, d);
    d = fmaf(a.z, b.z, d);
    d = fmaf(a.w, b.w, d);
}

#define XSTR 132
#define WSTR 132

__global__ void __launch_bounds__(256) k_gemm(
    const float* __restrict__ A,
    const float* __restrict__ W0, const float* __restrict__ B0,
    const float* __restrict__ W1, const float* __restrict__ B1,
    const float* __restrict__ W2,
    float* __restrict__ O0, float* __restrict__ O1, float* __restrict__ O2,
    int outs_total)
{
    extern __shared__ float sm[];
    float* sW = sm;                    // 64*WSTR
    float* sX = sW + 64*WSTR;          // 128*XSTR
    float* sB = sX + 128*XSTR;         // 64

    const int tid = threadIdx.x;
    const int ob  = blockIdx.y * 64;
    const int rows = min(64, outs_total - ob);   // 64 or 16 (skip chunk)

    const float* Wsrc; const float* Bsrc;
    if (ob < 128)      { Wsrc = W0 + ob*128;           Bsrc = B0 + ob; }
    else if (ob < 256) { Wsrc = W1 + (ob-128)*128;     Bsrc = B1 + (ob-128); }
    else               { Wsrc = W2;                    Bsrc = nullptr; }

    // W chunk -> smem (row stride WSTR floats)
    const float4* wg = (const float4*)Wsrc;
    for (int i = tid; i < rows*32; i += 256) {
        int r = i >> 5, q = i & 31;
        ((float4*)(sW + r*WSTR))[q] = wg[r*32 + q];
    }
    if (tid < 64) sB[tid] = (tid < rows && Bsrc) ? Bsrc[tid] : 0.f;

    // X tile (128 nodes) -> smem
    const int n0 = blockIdx.x * 128;
    for (int i = tid; i < 4096; i += 256) {
        int r = i >> 5, q = i & 31;
        int n = n0 + r;
        float4 v = make_float4(0.f, 0.f, 0.f, 0.f);
        if (n < NN) v = ((const float4*)(A + (size_t)n * 128))[q];
        ((float4*)(sX + r*XSTR))[q] = v;
    }
    __syncthreads();

    const int tx = tid & 15;          // node lane: nodes tx + 16*i, i=0..7
    const int ty = tid >> 4;          // out group: outs ty*4 .. ty*4+3

    if (ty * 4 < rows) {
        float acc[8][4];
        #pragma unroll
        for (int i = 0; i < 8; i++)
            #pragma unroll
            for (int j = 0; j < 4; j++) acc[i][j] = 0.f;

        const float4* wp0 = (const float4*)(sW + (ty*4 + 0) * WSTR);
        const float4* wp1 = (const float4*)(sW + (ty*4 + 1) * WSTR);
        const float4* wp2 = (const float4*)(sW + (ty*4 + 2) * WSTR);
        const float4* wp3 = (const float4*)(sW + (ty*4 + 3) * WSTR);

        #pragma unroll 2
        for (int kq = 0; kq < 32; kq++) {
            float4 wv0 = wp0[kq], wv1 = wp1[kq], wv2 = wp2[kq], wv3 = wp3[kq];
            #pragma unroll
            for (int i = 0; i < 8; i++) {
                float4 xv = ((const float4*)(sX + (tx + 16*i) * XSTR))[kq];
                dot4(xv, wv0, acc[i][0]);
                dot4(xv, wv1, acc[i][1]);
                dot4(xv, wv2, acc[i][2]);
                dot4(xv, wv3, acc[i][3]);
            }
        }

        #pragma unroll
        for (int j = 0; j < 4; j++) {
            int o = ob + ty*4 + j;
            float bv = sB[ty*4 + j];
            #pragma unroll
            for (int i = 0; i < 8; i++) {
                int n = n0 + tx + 16*i;
                if (n >= NN) continue;
                float v = acc[i][j] + bv;
                if (o < 128)      O0[(size_t)n * 128 + o]       = v;
                else if (o < 256) O1[(size_t)n * 128 + (o-128)] = v;
                else              O2[(size_t)n * 16  + (o-256)] = v;
            }
        }
    }
}

// ---------------- warp-per-node attention aggregation -----------------------
// lane = (head h = lane>>2, channel group cg = lane&3 -> channels cg*4..+3).
// One edge = one warp: LDG.128 gather, float4 leaky+dot, 2-SHFL head reduce.
// Self-loop score is the softmax baseline (shift-invariant).
__device__ __forceinline__ float grp_sum4(float p) {
    p += __shfl_xor_sync(0xffffffffu, p, 1);
    p += __shfl_xor_sync(0xffffffffu, p, 2);
    return p;
}
__device__ __forceinline__ float4 lrelu4(float4 v) {
    v.x = (v.x > 0.f) ? v.x : NEG * v.x;
    v.y = (v.y > 0.f) ? v.y : NEG * v.y;
    v.z = (v.z > 0.f) ? v.z : NEG * v.z;
    v.w = (v.w > 0.f) ? v.w : NEG * v.w;
    return v;
}
__device__ __forceinline__ float dot4s(const float4 a, const float4 b) {
    return fmaf(a.x, b.x, fmaf(a.y, b.y, fmaf(a.z, b.z, a.w * b.w)));
}

__device__ __forceinline__ void agg_warp_body(
    const float* __restrict__ xlbuf, const float* __restrict__ xrbuf,
    const float* __restrict__ att,
    int d, int lane, float4& acc_out, float& den_out)
{
    const int* __restrict__ csr = g_csr;
    const float4 att4 = *(const float4*)(att   + lane * 4);
    const float4 xr4  = *(const float4*)(xrbuf + (size_t)d * 128 + lane * 4);
    const float4 xs4  = *(const float4*)(xlbuf + (size_t)d * 128 + lane * 4);

    // self-loop -> baseline
    const float m0 = grp_sum4(dot4s(lrelu4(make_float4(
        xs4.x + xr4.x, xs4.y + xr4.y, xs4.z + xr4.z, xs4.w + xr4.w)), att4));
    float den = 1.f;
    float4 acc = xs4;

    const int beg = g_rowptr[d], end = g_rowptr[d + 1];
    int j = beg;
    for (; j + 2 <= end; j += 2) {
        int ia = csr[j], ib = csr[j + 1];
        float4 xa = *(const float4*)(xlbuf + (size_t)ia * 128 + lane * 4);
        float4 xb = *(const float4*)(xlbuf + (size_t)ib * 128 + lane * 4);
        float4 ea = lrelu4(make_float4(xa.x + xr4.x, xa.y + xr4.y, xa.z + xr4.z, xa.w + xr4.w));
        float4 eb = lrelu4(make_float4(xb.x + xr4.x, xb.y + xr4.y, xb.z + xr4.z, xb.w + xr4.w));
        float sa = grp_sum4(dot4s(ea, att4));
        float sb = grp_sum4(dot4s(eb, att4));
        float wa = __expf(sa - m0);
        float wb = __expf(sb - m0);
        den += wa + wb;
        acc.x = fmaf(wa, xa.x, fmaf(wb, xb.x, acc.x));
        acc.y = fmaf(wa, xa.y, fmaf(wb, xb.y, acc.y));
        acc.z = fmaf(wa, xa.z, fmaf(wb, xb.z, acc.z));
        acc.w = fmaf(wa, xa.w, fmaf(wb, xb.w, acc.w));
    }
    if (j < end) {
        int ia = csr[j];
        float4 xa = *(const float4*)(xlbuf + (size_t)ia * 128 + lane * 4);
        float4 ea = lrelu4(make_float4(xa.x + xr4.x, xa.y + xr4.y, xa.z + xr4.z, xa.w + xr4.w));
        float sa = grp_sum4(dot4s(ea, att4));
        float wa = __expf(sa - m0);
        den += wa;
        acc.x = fmaf(wa, xa.x, acc.x);
        acc.y = fmaf(wa, xa.y, acc.y);
        acc.z = fmaf(wa, xa.z, acc.z);
        acc.w = fmaf(wa, xa.w, acc.w);
    }
    acc_out = acc; den_out = den;
}

__global__ void __launch_bounds__(256) k_agg1(
    const float* __restrict__ att,  const float* __restrict__ bias,
    const float* __restrict__ bnw,  const float* __restrict__ bnb,
    const float* __restrict__ bnrm, const float* __restrict__ bnrv)
{
    const int warp = threadIdx.x >> 5;
    const int lane = threadIdx.x & 31;
    const int d = blockIdx.x * 8 + warp;
    if (d >= NN) return;

    float4 acc; float den;
    agg_warp_body(g_xl1, g_xr1, att, d, lane, acc, den);

    const float inv = 1.f / den;
    float4 b4  = *(const float4*)(bias + lane * 4);
    float4 w4  = *(const float4*)(bnw  + lane * 4);
    float4 c4  = *(const float4*)(bnb  + lane * 4);
    float4 m4  = *(const float4*)(bnrm + lane * 4);
    float4 v4  = *(const float4*)(bnrv + lane * 4);

    float4 o;
    o.x = (acc.x * inv + b4.x - m4.x) * rsqrtf(v4.x + 1e-5f) * w4.x + c4.x;
    o.y = (acc.y * inv + b4.y - m4.y) * rsqrtf(v4.y + 1e-5f) * w4.y + c4.y;
    o.z = (acc.z * inv + b4.z - m4.z) * rsqrtf(v4.z + 1e-5f) * w4.z + c4.z;
    o.w = (acc.w * inv + b4.w - m4.w) * rsqrtf(v4.w + 1e-5f) * w4.w + c4.w;
    o.x = (o.x > 0.f) ? o.x : (__expf(o.x) - 1.f);
    o.y = (o.y > 0.f) ? o.y : (__expf(o.y) - 1.f);
    o.z = (o.z > 0.f) ? o.z : (__expf(o.z) - 1.f);
    o.w = (o.w > 0.f) ? o.w : (__expf(o.w) - 1.f);

    *(float4*)(g_h1 + (size_t)d * 128 + lane * 4) = o;
}

__global__ void __launch_bounds__(256) k_agg2(
    const float* __restrict__ att, const float* __restrict__ bias2,
    const float* __restrict__ lnw, const float* __restrict__ lnb,
    float* __restrict__ out)
{
    const int warp = threadIdx.x >> 5;
    const int lane = threadIdx.x & 31;
    const int d = blockIdx.x * 8 + warp;
    if (d >= NN) return;

    float4 acc; float den;
    agg_warp_body(g_xl2, g_xr2, att, d, lane, acc, den);

    const float inv = 1.f / den;
    float4 v = make_float4(acc.x * inv, acc.y * inv, acc.z * inv, acc.w * inv);

    // mean over 8 heads: butterfly over lanes differing in bits 2..4
    #pragma unroll
    for (int s = 4; s <= 16; s <<= 1) {
        v.x += __shfl_xor_sync(0xffffffffu, v.x, s);
        v.y += __shfl_xor_sync(0xffffffffu, v.y, s);
        v.z += __shfl_xor_sync(0xffffffffu, v.z, s);
        v.w += __shfl_xor_sync(0xffffffffu, v.w, s);
    }
    const int cg = lane & 3;
    float4 b2 = *(const float4*)(bias2 + cg * 4);
    float4 xr = *(const float4*)(g_xres + (size_t)d * 16 + cg * 4);
    v.x = v.x * 0.125f + b2.x + xr.x;
    v.y = v.y * 0.125f + b2.y + xr.y;
    v.z = v.z * 0.125f + b2.z + xr.z;
    v.w = v.w * 0.125f + b2.w + xr.w;

    // LayerNorm over 16 channels (4 components x 4 cg lanes)
    float mu = (v.x + v.y) + (v.z + v.w);
    mu += __shfl_xor_sync(0xffffffffu, mu, 1);
    mu += __shfl_xor_sync(0xffffffffu, mu, 2);
    mu *= (1.f / 16.f);
    float dx = v.x - mu, dy = v.y - mu, dz = v.z - mu, dw = v.w - mu;
    float var = (dx * dx + dy * dy) + (dz * dz + dw * dw);
    var += __shfl_xor_sync(0xffffffffu, var, 1);
    var += __shfl_xor_sync(0xffffffffu, var, 2);
    var *= (1.f / 16.f);
    float rs = rsqrtf(var + 1e-5f);

    if (lane < 4) {
        float4 lw = *(const float4*)(lnw + cg * 4);
        float4 lb = *(const float4*)(lnb + cg * 4);
        float4 o;
        o.x = dx * rs * lw.x + lb.x;
        o.y = dy * rs * lw.y + lb.y;
        o.z = dz * rs * lw.z + lb.z;
        o.w = dw * rs * lw.w + lb.w;
        *(float4*)(out + (size_t)d * 16 + cg * 4) = o;
    }
}

// ---------------- host ------------------------------------------------------
extern "C" void kernel_launch(void* const* d_in, const int* in_sizes, int n_in,
                              void* d_out, int out_size)
{
    const float* x     = (const float*)d_in[0];
    const int*   ei    = (const int*)d_in[1];      // int32: JAX x64 disabled
    const float* Wl1   = (const float*)d_in[2];
    const float* bl1   = (const float*)d_in[3];
    const float* Wr1   = (const float*)d_in[4];
    const float* br1   = (const float*)d_in[5];
    const float* att1  = (const float*)d_in[6];
    const float* bias1 = (const float*)d_in[7];
    const float* bnw   = (const float*)d_in[8];
    const float* bnb   = (const float*)d_in[9];
    const float* bnrm  = (const float*)d_in[10];
    const float* bnrv  = (const float*)d_in[11];
    const float* Wl2   = (const float*)d_in[12];
    const float* bl2   = (const float*)d_in[13];
    const float* Wr2   = (const float*)d_in[14];
    const float* br2   = (const float*)d_in[15];
    const float* att2  = (const float*)d_in[16];
    const float* bias2 = (const float*)d_in[17];
    const float* Wskip = (const float*)d_in[18];
    const float* lnw   = (const float*)d_in[19];
    const float* lnb   = (const float*)d_in[20];
    float*       out   = (float*)d_out;

    float *xl1, *xr1, *h1, *xl2, *xr2, *xres;
    cudaGetSymbolAddress((void**)&xl1,  g_xl1);
    cudaGetSymbolAddress((void**)&xr1,  g_xr1);
    cudaGetSymbolAddress((void**)&h1,   g_h1);
    cudaGetSymbolAddress((void**)&xl2,  g_xl2);
    cudaGetSymbolAddress((void**)&xr2,  g_xr2);
    cudaGetSymbolAddress((void**)&xres, g_xres);

    const int smem = (64*WSTR + 128*XSTR + 64) * 4;   // ~101.6 KB
    cudaFuncSetAttribute(k_gemm, cudaFuncAttributeMaxDynamicSharedMemorySize, smem);

    // CSR build (recomputed each call; deterministic)
    k_zero_deg<<<(NN + 255) / 256, 256>>>();
    k_count<<<(EE + 255) / 256, 256>>>(ei);
    k_scan<<<1, 1024>>>();
    k_scatter<<<(EE + 255) / 256, 256>>>(ei);

    const int NTILES = (NN + 127) / 128;   // 391
    const int AGG_GRID = (NN + 7) / 8;     // 6250

    // conv1 transforms + skip projection (outs = 128+128+16 = 272 -> 5 chunks)
    k_gemm<<<dim3(NTILES, 5), 256, smem>>>(x, Wl1, bl1, Wr1, br1, Wskip,
                                           xl1, xr1, xres, 272);
    // conv1 aggregation + BN + ELU
    k_agg1<<<AGG_GRID, 256>>>(att1, bias1, bnw, bnb, bnrm, bnrv);

    // conv2 transforms (outs = 256 -> 4 chunks)
    k_gemm<<<dim3(NTILES, 4), 256, smem>>>(h1, Wl2, bl2, Wr2, br2, nullptr,
                                           xl2, xr2, nullptr, 256);
    // conv2 aggregation + head-mean + skip + LayerNorm
    k_agg2<<<AGG_GRID, 256>>>(att2, bias2, lnw, lnb, out);
}